// round 17
// baseline (speedup 1.0000x reference)
#include <cuda_runtime.h>
#include <cuda_bf16.h>
#include <cstdint>

#define I_DIM 128
#define O_DIM 64
#define R_DIM 7
#define T_DIM 4
#define MAX_N 300000
#define MAX_E 4000000

// ---------------- scratch (device globals; no runtime allocation) ----------
__device__ int           g_cnt[MAX_N * R_DIM];    // per-(dst,rel) counts (mean denom)
__device__ int           g_scnt[MAX_N * R_DIM];   // per-(src,rel) counts
__device__ int           g_soff[MAX_N * R_DIM];   // per-(src,rel) segment start
__device__ int           g_scur[MAX_N * R_DIM];   // scatter cursors
__device__ int           g_srcoff[MAX_N];         // per-src exclusive prefix (degree)
__device__ int           g_order[MAX_N];
__device__ int           g_tcnt[T_DIM];
__device__ int           g_offsets[T_DIM + 1];
__device__ int           g_cursor[T_DIM];
__device__ int           g_blockBase[T_DIM + 1];
__device__ int           g_bsum[1024];
__device__ int           g_sorted[MAX_E];         // dst ids, sorted by (src,et)
__device__ __nv_bfloat16 g_xhi[(size_t)MAX_N * I_DIM];
__device__ __nv_bfloat16 g_xlo[(size_t)MAX_N * I_DIM];
__device__ __nv_bfloat16 g_whi[R_DIM * O_DIM * I_DIM];   // [r][o][i] K-major
__device__ __nv_bfloat16 g_wlo[R_DIM * O_DIM * I_DIM];
__device__ __nv_bfloat16 g_rwhi[T_DIM * O_DIM * I_DIM];
__device__ __nv_bfloat16 g_rwlo[T_DIM * O_DIM * I_DIM];

// ---------------- warp-MMA helpers (sm_80+ base features, OK on sm_103) -----
__device__ __forceinline__ uint32_t smem_u32(const void* p) {
    uint32_t a;
    asm("{ .reg .u64 t; cvta.to.shared.u64 t, %1; cvt.u32.u64 %0, t; }"
        : "=r"(a) : "l"(p));
    return a;
}
__device__ __forceinline__ void ldsm4(uint32_t* r, uint32_t addr) {
    asm volatile("ldmatrix.sync.aligned.m8n8.x4.shared.b16 {%0,%1,%2,%3}, [%4];"
                 : "=r"(r[0]), "=r"(r[1]), "=r"(r[2]), "=r"(r[3]) : "r"(addr));
}
__device__ __forceinline__ void ldsm2(uint32_t* r, uint32_t addr) {
    asm volatile("ldmatrix.sync.aligned.m8n8.x2.shared.b16 {%0,%1}, [%2];"
                 : "=r"(r[0]), "=r"(r[1]) : "r"(addr));
}
__device__ __forceinline__ void mma16816(float* c, const uint32_t* a, const uint32_t* b) {
    asm volatile(
        "mma.sync.aligned.m16n8k16.row.col.f32.bf16.bf16.f32 "
        "{%0,%1,%2,%3}, {%4,%5,%6,%7}, {%8,%9}, {%0,%1,%2,%3};"
        : "+f"(c[0]), "+f"(c[1]), "+f"(c[2]), "+f"(c[3])
        : "r"(a[0]), "r"(a[1]), "r"(a[2]), "r"(a[3]), "r"(b[0]), "r"(b[1]));
}

// smem layout (bytes): rows are 128 bf16 = 256B data; pitch 272 = 256+16 pad.
#define A_PITCH 272
#define SM_A_HI 0
#define SM_A_LO 34816              // 128*272
#define SM_B_HI 69632              // B hi (64*272) then B lo; also reused as
#define SM_B_LO 87040              //   the 128x64 fp32 stage tile (128*272)
#define SM_STAGE 69632
#define SMEM_DYN 104448

// ---------------- conversion kernels ----------------------------------------
__global__ void convert_x_kernel(const float* __restrict__ x, int total2) {
    int i = blockIdx.x * 256 + threadIdx.x;
    if (i < total2) {
        float2 v = ((const float2*)x)[i];
        __nv_bfloat16 h0 = __float2bfloat16(v.x);
        __nv_bfloat16 h1 = __float2bfloat16(v.y);
        __nv_bfloat162 hh; hh.x = h0; hh.y = h1;
        __nv_bfloat162 ll;
        ll.x = __float2bfloat16(v.x - __bfloat162float(h0));
        ll.y = __float2bfloat16(v.y - __bfloat162float(h1));
        ((__nv_bfloat162*)g_xhi)[i] = hh;
        ((__nv_bfloat162*)g_xlo)[i] = ll;
    }
}

__global__ void convert_w_kernel(const float* __restrict__ Wrel,
                                 const float* __restrict__ Wroot) {
    int i = blockIdx.x * 256 + threadIdx.x;
    if (i >= (R_DIM + T_DIM) * O_DIM * I_DIM) return;
    int grp = i >> 13;            // 8192 = 64*128
    int rem = i & 8191;
    int nrow = rem >> 7;          // O index
    int k = rem & 127;            // I index
    float v;
    if (grp < R_DIM) v = Wrel[((size_t)grp * I_DIM + k) * O_DIM + nrow];
    else             v = Wroot[((size_t)(grp - R_DIM) * I_DIM + k) * O_DIM + nrow];
    __nv_bfloat16 h = __float2bfloat16(v);
    __nv_bfloat16 l = __float2bfloat16(v - __bfloat162float(h));
    if (grp < R_DIM) { g_whi[i] = h; g_wlo[i] = l; }
    else { g_rwhi[(grp - R_DIM) * 8192 + rem] = h; g_rwlo[(grp - R_DIM) * 8192 + rem] = l; }
}

// ---------------- small prep kernels ---------------------------------------
__global__ void edge_count_kernel(const int* __restrict__ ei,
                                  const int* __restrict__ etype, int E) {
    int e = blockIdx.x * 256 + threadIdx.x;
    if (e < E) {
        int et = etype[e];
        atomicAdd(&g_cnt[ei[E + e] * R_DIM + et], 1);   // dst side (denominators)
        atomicAdd(&g_scnt[ei[e] * R_DIM + et], 1);      // src side (push CSR)
    }
}

__global__ void type_hist_kernel(const int* __restrict__ nt, int n) {
    __shared__ int s[T_DIM];
    if (threadIdx.x < T_DIM) s[threadIdx.x] = 0;
    __syncthreads();
    int i = blockIdx.x * 256 + threadIdx.x;
    if (i < n) atomicAdd(&s[nt[i]], 1);
    __syncthreads();
    if (threadIdx.x < T_DIM) atomicAdd(&g_tcnt[threadIdx.x], s[threadIdx.x]);
}

__global__ void scan_kernel() {
    if (threadIdx.x == 0 && blockIdx.x == 0) {
        int off = 0, bb = 0;
        g_offsets[0] = 0;
        g_blockBase[0] = 0;
        for (int t = 0; t < T_DIM; t++) {
            int c = g_tcnt[t];
            g_cursor[t] = off;
            off += c;
            g_offsets[t + 1] = off;
            bb += (c + 127) >> 7;
            g_blockBase[t + 1] = bb;
        }
    }
}

__global__ void type_scatter_kernel(const int* __restrict__ nt, int n) {
    __shared__ int s_cnt[T_DIM];
    __shared__ int s_base[T_DIM];
    if (threadIdx.x < T_DIM) s_cnt[threadIdx.x] = 0;
    __syncthreads();
    int i = blockIdx.x * 256 + threadIdx.x;
    int t = 0, r = 0;
    bool valid = (i < n);
    if (valid) { t = nt[i]; r = atomicAdd(&s_cnt[t], 1); }
    __syncthreads();
    if (threadIdx.x < T_DIM)
        s_base[threadIdx.x] = atomicAdd(&g_cursor[threadIdx.x], s_cnt[threadIdx.x]);
    __syncthreads();
    if (valid) g_order[s_base[t] + r] = i;
}

// ---------------- src-CSR: scan over per-src degree -------------------------
__global__ void scan_blocks_kernel(int n) {
    __shared__ int wsum[16];
    int i = blockIdx.x * 512 + threadIdx.x;
    int lane = threadIdx.x & 31, wid = threadIdx.x >> 5;
    int v = 0;
    if (i < n) {
#pragma unroll
        for (int r = 0; r < R_DIM; r++) v += g_scnt[i * R_DIM + r];
    }
    int x = v;
#pragma unroll
    for (int d = 1; d < 32; d <<= 1) {
        int y = __shfl_up_sync(0xFFFFFFFF, x, d);
        if (lane >= d) x += y;
    }
    if (lane == 31) wsum[wid] = x;
    __syncthreads();
    if (wid == 0) {
        int s = (lane < 16) ? wsum[lane] : 0;
#pragma unroll
        for (int d = 1; d < 16; d <<= 1) {
            int y = __shfl_up_sync(0xFFFFFFFF, s, d);
            if (lane >= d) s += y;
        }
        if (lane < 16) wsum[lane] = s;
    }
    __syncthreads();
    int base = (wid > 0) ? wsum[wid - 1] : 0;
    if (i < n) g_srcoff[i] = base + x - v;          // exclusive within block
    if (threadIdx.x == 511) g_bsum[blockIdx.x] = base + x;
}

__global__ void scan_top_kernel(int nblk) {
    __shared__ int wsum[32];
    int i = threadIdx.x;                   // single block, 1024 threads
    int lane = i & 31, wid = i >> 5;
    int v = (i < nblk) ? g_bsum[i] : 0;
    int x = v;
#pragma unroll
    for (int d = 1; d < 32; d <<= 1) {
        int y = __shfl_up_sync(0xFFFFFFFF, x, d);
        if (lane >= d) x += y;
    }
    if (lane == 31) wsum[wid] = x;
    __syncthreads();
    if (wid == 0) {
        int s = wsum[lane];
#pragma unroll
        for (int d = 1; d < 32; d <<= 1) {
            int y = __shfl_up_sync(0xFFFFFFFF, s, d);
            if (lane >= d) s += y;
        }
        wsum[lane] = s;
    }
    __syncthreads();
    int base = (wid > 0) ? wsum[wid - 1] : 0;
    if (i < nblk) g_bsum[i] = base + x - v;
}

// finalize srcoff; build per-(src,et) segment starts + cursors
__global__ void soff_kernel(int n) {
    int i = blockIdx.x * 512 + threadIdx.x;
    if (i < n) {
        int base = g_srcoff[i] + g_bsum[i >> 9];
        g_srcoff[i] = base;
#pragma unroll
        for (int r = 0; r < R_DIM; r++) {
            g_soff[i * R_DIM + r] = base;
            g_scur[i * R_DIM + r] = base;
            base += g_scnt[i * R_DIM + r];
        }
    }
}

__global__ void sort_scatter_kernel(const int* __restrict__ ei,
                                    const int* __restrict__ etype, int E) {
    int e = blockIdx.x * 256 + threadIdx.x;
    if (e < E) {
        int pos = atomicAdd(&g_scur[ei[e] * R_DIM + etype[e]], 1);
        g_sorted[pos] = ei[E + e];       // dst id; (src,et) implied by segment
    }
}

// ---------------- shared device helpers for the MMA GEMMs -------------------
struct Frag { float acc[2][4][4]; };

__device__ __forceinline__ void mma_tile_compute(Frag& F, uint32_t sb,
                                                 int mgroup, int nhalf, int lane) {
#pragma unroll
    for (int mt = 0; mt < 2; mt++)
#pragma unroll
        for (int nt = 0; nt < 4; nt++)
#pragma unroll
            for (int q = 0; q < 4; q++) F.acc[mt][nt][q] = 0.f;

    const int lr = lane & 7, g = lane >> 3;
#pragma unroll
    for (int ks = 0; ks < 8; ks++) {
        const int k0 = ks * 16;
        uint32_t ahi[2][4], alo[2][4];
#pragma unroll
        for (int mt = 0; mt < 2; mt++) {
            int row = mgroup * 32 + mt * 16 + lr + (g & 1) * 8;
            uint32_t aaddr = sb + (uint32_t)row * A_PITCH + (uint32_t)(k0 + (g >> 1) * 8) * 2;
            ldsm4(ahi[mt], aaddr + SM_A_HI);
            ldsm4(alo[mt], aaddr + SM_A_LO);
        }
        uint32_t bhi[4][2], blo[4][2];
#pragma unroll
        for (int nt = 0; nt < 4; nt++) {
            int nrow = nhalf * 32 + nt * 8 + lr;
            uint32_t baddr = sb + (uint32_t)nrow * A_PITCH + (uint32_t)(k0 + (g & 1) * 8) * 2;
            ldsm2(bhi[nt], baddr + SM_B_HI);
            ldsm2(blo[nt], baddr + SM_B_LO);
        }
#pragma unroll
        for (int mt = 0; mt < 2; mt++)
#pragma unroll
            for (int nt = 0; nt < 4; nt++) {
                mma16816(F.acc[mt][nt], ahi[mt], bhi[nt]);
                mma16816(F.acc[mt][nt], ahi[mt], blo[nt]);
                mma16816(F.acc[mt][nt], alo[mt], bhi[nt]);
            }
    }
}

// ---------------- h+push: per relation, MMA then push rows into out ---------
// Stage tile: 128 rows x 68-float pitch (272B) in the consumed B region.
extern "C" __global__ void __launch_bounds__(256, 2)
h_push_kernel(float* __restrict__ out, int n) {
    extern __shared__ __align__(16) char sm[];
    const uint32_t sb = smem_u32(sm);
    const int tid = threadIdx.x, wid = tid >> 5, lane = tid & 31;
    const int mgroup = wid & 3, nhalf = wid >> 2;
    const int n0 = blockIdx.x * 128;
    float* stage = (float*)(sm + SM_STAGE);

    // Load A (x hi/lo): 128 rows x 16 chunks of 16B, pitch 272
#pragma unroll
    for (int it = 0; it < 8; it++) {
        int idx = tid + it * 256;           // 0..2047
        int row = idx >> 4, c = idx & 15;
        int node = n0 + row;
        uint4 vh = make_uint4(0, 0, 0, 0), vl = vh;
        if (node < n) {
            vh = ((const uint4*)(g_xhi + (size_t)node * I_DIM))[c];
            vl = ((const uint4*)(g_xlo + (size_t)node * I_DIM))[c];
        }
        *(uint4*)(sm + SM_A_HI + row * A_PITCH + c * 16) = vh;
        *(uint4*)(sm + SM_A_LO + row * A_PITCH + c * 16) = vl;
    }

    Frag F;
    for (int r = 0; r < R_DIM; r++) {
        __syncthreads();                 // protect B region (stage reads done)
        // Load B_r (W hi/lo): 64 rows x 16 chunks, pitch 272
#pragma unroll
        for (int it = 0; it < 4; it++) {
            int idx = tid + it * 256;
            int nr = idx >> 4, c = idx & 15;
            uint4 vh = ((const uint4*)(g_whi + ((size_t)r * O_DIM + nr) * I_DIM))[c];
            uint4 vl = ((const uint4*)(g_wlo + ((size_t)r * O_DIM + nr) * I_DIM))[c];
            *(uint4*)(sm + SM_B_HI + nr * A_PITCH + c * 16) = vh;
            *(uint4*)(sm + SM_B_LO + nr * A_PITCH + c * 16) = vl;
        }
        __syncthreads();

        mma_tile_compute(F, sb, mgroup, nhalf, lane);
        __syncthreads();                 // B consumed by all warps; reuse as stage

        // stage fragments: 128 rows x 64 cols fp32, pitch 68 floats
#pragma unroll
        for (int mt = 0; mt < 2; mt++) {
            int row = mgroup * 32 + mt * 16 + (lane >> 2);
#pragma unroll
            for (int nt = 0; nt < 4; nt++) {
                int col = nhalf * 32 + nt * 8 + (lane & 3) * 2;
                *(float2*)&stage[row * 68 + col] =
                    make_float2(F.acc[mt][nt][0], F.acc[mt][nt][1]);
                *(float2*)&stage[(row + 8) * 68 + col] =
                    make_float2(F.acc[mt][nt][2], F.acc[mt][nt][3]);
            }
        }
        __syncthreads();

        // push: warp wid owns nodes [wid*16, wid*16+16); half-warp per edge
        const int half = lane >> 4, l16 = lane & 15;
        for (int i = 0; i < 16; i++) {
            int node = n0 + wid * 16 + i;
            if (node >= n) break;
            int seg = __ldg(&g_soff[node * R_DIM + r]);
            int len = __ldg(&g_scnt[node * R_DIM + r]);
            if (len == 0) continue;
            float4 v = *(float4*)&stage[(wid * 16 + i) * 68 + l16 * 4];
            for (int j = half; j < len; j += 2) {
                int dst = __ldg(&g_sorted[seg + j]);
                float inv = 1.0f / (float)__ldg(&g_cnt[dst * R_DIM + r]);
                float* op = out + (size_t)dst * O_DIM + l16 * 4;
                asm volatile("red.global.add.v4.f32 [%0], {%1, %2, %3, %4};"
                             :: "l"(op), "f"(v.x * inv), "f"(v.y * inv),
                                "f"(v.z * inv), "f"(v.w * inv)
                             : "memory");
            }
        }
    }
}

// ---------------- root: out = x @ W_root[type] + b_root[type] ---------------
extern "C" __global__ void __launch_bounds__(256, 2)
root_mma_kernel(const float* __restrict__ broot, float* __restrict__ out) {
    extern __shared__ __align__(16) char sm[];
    __shared__ int s_nid[128];
    const uint32_t sb = smem_u32(sm);
    const int tid = threadIdx.x, wid = tid >> 5, lane = tid & 31;
    const int mgroup = wid & 3, nhalf = wid >> 2;

    int b = blockIdx.x;
    int t = -1, tile = 0;
#pragma unroll
    for (int tt = 0; tt < T_DIM; tt++) {
        int lo = g_blockBase[tt], hi = g_blockBase[tt + 1];
        if (t < 0 && b >= lo && b < hi) { t = tt; tile = b - lo; }
    }
    if (t < 0) return;
    int row0 = g_offsets[t] + tile * 128;
    int rowEnd = g_offsets[t + 1];

    if (tid < 128) {
        int rr = row0 + tid;
        s_nid[tid] = (rr < rowEnd) ? g_order[rr] : -1;
    }
    __syncthreads();

#pragma unroll
    for (int it = 0; it < 8; it++) {
        int idx = tid + it * 256;
        int row = idx >> 4, c = idx & 15;
        int node = s_nid[row];
        uint4 vh = make_uint4(0, 0, 0, 0), vl = vh;
        if (node >= 0) {
            vh = ((const uint4*)(g_xhi + (size_t)node * I_DIM))[c];
            vl = ((const uint4*)(g_xlo + (size_t)node * I_DIM))[c];
        }
        *(uint4*)(sm + SM_A_HI + row * A_PITCH + c * 16) = vh;
        *(uint4*)(sm + SM_A_LO + row * A_PITCH + c * 16) = vl;
    }
#pragma unroll
    for (int it = 0; it < 4; it++) {
        int idx = tid + it * 256;
        int nr = idx >> 4, c = idx & 15;
        uint4 vh = ((const uint4*)(g_rwhi + ((size_t)t * O_DIM + nr) * I_DIM))[c];
        uint4 vl = ((const uint4*)(g_rwlo + ((size_t)t * O_DIM + nr) * I_DIM))[c];
        *(uint4*)(sm + SM_B_HI + nr * A_PITCH + c * 16) = vh;
        *(uint4*)(sm + SM_B_LO + nr * A_PITCH + c * 16) = vl;
    }
    __syncthreads();

    Frag F;
    mma_tile_compute(F, sb, mgroup, nhalf, lane);

#pragma unroll
    for (int mt = 0; mt < 2; mt++) {
        int row = mgroup * 32 + mt * 16 + (lane >> 2);
#pragma unroll
        for (int nt = 0; nt < 4; nt++) {
            int col = nhalf * 32 + nt * 8 + (lane & 3) * 2;
            float2 bias = *(const float2*)(broot + (size_t)t * O_DIM + col);
            int nodeA = s_nid[row], nodeB = s_nid[row + 8];
            if (nodeA >= 0)
                *(float2*)(out + (size_t)nodeA * O_DIM + col) =
                    make_float2(F.acc[mt][nt][0] + bias.x, F.acc[mt][nt][1] + bias.y);
            if (nodeB >= 0)
                *(float2*)(out + (size_t)nodeB * O_DIM + col) =
                    make_float2(F.acc[mt][nt][2] + bias.x, F.acc[mt][nt][3] + bias.y);
        }
    }
}

// ---------------- launch ----------------------------------------------------
extern "C" void kernel_launch(void* const* d_in, const int* in_sizes, int n_in,
                              void* d_out, int out_size) {
    const float* x     = (const float*)d_in[0];
    const int*   ei    = (const int*)d_in[1];
    const int*   et    = (const int*)d_in[2];
    const int*   nt    = (const int*)d_in[3];
    const float* Wrel  = (const float*)d_in[4];
    const float* Wroot = (const float*)d_in[5];
    const float* broot = (const float*)d_in[6];
    float*       out   = (float*)d_out;

    int n = in_sizes[0] / I_DIM;
    int E = in_sizes[2];

    void *p_cnt = nullptr, *p_scnt = nullptr, *p_tcnt = nullptr;
    cudaGetSymbolAddress(&p_cnt, g_cnt);
    cudaGetSymbolAddress(&p_scnt, g_scnt);
    cudaGetSymbolAddress(&p_tcnt, g_tcnt);
    cudaMemsetAsync(p_cnt, 0, sizeof(int) * (size_t)n * R_DIM, 0);
    cudaMemsetAsync(p_scnt, 0, sizeof(int) * (size_t)n * R_DIM, 0);
    cudaMemsetAsync(p_tcnt, 0, sizeof(int) * T_DIM, 0);

    cudaFuncSetAttribute(h_push_kernel,
                         cudaFuncAttributeMaxDynamicSharedMemorySize, SMEM_DYN);
    cudaFuncSetAttribute(root_mma_kernel,
                         cudaFuncAttributeMaxDynamicSharedMemorySize, SMEM_DYN);

    int total2 = n * (I_DIM / 2);
    convert_x_kernel<<<(total2 + 255) / 256, 256>>>(x, total2);
    convert_w_kernel<<<((R_DIM + T_DIM) * O_DIM * I_DIM + 255) / 256, 256>>>(Wrel, Wroot);

    // counts + src-CSR
    edge_count_kernel<<<(E + 255) / 256, 256>>>(ei, et, E);
    int nblk = (n + 511) / 512;                        // <= 1024
    scan_blocks_kernel<<<nblk, 512>>>(n);
    scan_top_kernel<<<1, 1024>>>(nblk);
    soff_kernel<<<nblk, 512>>>(n);
    sort_scatter_kernel<<<(E + 255) / 256, 256>>>(ei, et, E);

    // root first: initializes every out row (pushes then accumulate into it)
    type_hist_kernel<<<(n + 255) / 256, 256>>>(nt, n);
    scan_kernel<<<1, 32>>>();
    type_scatter_kernel<<<(n + 255) / 256, 256>>>(nt, n);
    int gemm_blocks = (n + 127) / 128;
    root_mma_kernel<<<gemm_blocks + T_DIM, 256, SMEM_DYN>>>(broot, out);

    h_push_kernel<<<gemm_blocks, 256, SMEM_DYN>>>(out, n);
}